// round 17
// baseline (speedup 1.0000x reference)
#include <cuda_runtime.h>
#include <cuda_fp16.h>

#define NN 100000
#define EE 1600000
#define TPB 256

typedef unsigned long long u64;
typedef unsigned int u32;

// ---- scratch (__device__ globals; no allocations allowed) ----
__device__ __half   g_xlh[NN * 64];   // fp16 x @ Wl + bl (logits + messages)
__device__ __half   g_xrh[NN * 64];   // fp16 x @ Wr + br (logits only)
__device__ float4   g_denom[NN];      // per-head softmax denominators
__device__ float2   g_gate2[NN];      // {gate_sum, degree} per target
__device__ __align__(16) __half g_Wt[96 * 16];     // fp16 [We | Wg1]^T
__device__ __align__(16) __half g_W2t[128 * 64];   // fp16 [Wl | Wr]^T  (c,k)

__device__ __forceinline__ float sigmoidf_(float v) {
    return 1.f / (1.f + __expf(-v));
}
__device__ __forceinline__ float leaky(float m) { return fmaxf(m, 0.2f * m); }
__device__ __forceinline__ void red4(float* p, float a, float b, float c, float d) {
    asm volatile("red.global.add.v4.f32 [%0], {%1,%2,%3,%4};"
                 :: "l"(p), "f"(a), "f"(b), "f"(c), "f"(d) : "memory");
}
__device__ __forceinline__ void red2(float* p, float a, float b) {
    asm volatile("red.global.add.v2.f32 [%0], {%1,%2};"
                 :: "l"(p), "f"(a), "f"(b) : "memory");
}
__device__ __forceinline__ void cpa16(__half* smem_dst, const __half* gsrc) {
    unsigned d = (unsigned)__cvta_generic_to_shared(smem_dst);
    asm volatile("cp.async.ca.shared.global [%0], [%1], 16;"
                 :: "r"(d), "l"(gsrc) : "memory");
}
__device__ __forceinline__ unsigned h2_bits(__half2 v) {
    return *reinterpret_cast<unsigned*>(&v);
}
__device__ __forceinline__ void mma16816(float& d0, float& d1, float& d2, float& d3,
                                         u32 a0, u32 a1, u32 a2, u32 a3,
                                         u32 b0, u32 b1) {
    asm volatile(
        "mma.sync.aligned.m16n8k16.row.col.f32.f16.f16.f32 "
        "{%0,%1,%2,%3}, {%4,%5,%6,%7}, {%8,%9}, {%0,%1,%2,%3};"
        : "+f"(d0), "+f"(d1), "+f"(d2), "+f"(d3)
        : "r"(a0), "r"(a1), "r"(a2), "r"(a3), "r"(b0), "r"(b1));
}

// ---------------------------------------------------------------------------
// Kernel 0: build fp16 transposed weights:
//   g_Wt [96][16]  = [We | Wg1]^T       (edge-pass weights)
//   g_W2t[128][64] = [Wl | Wr]^T        (node-transform weights)
// ---------------------------------------------------------------------------
__global__ void k_wcvt(const float* __restrict__ We, const float* __restrict__ Wg1,
                       const float* __restrict__ Wl, const float* __restrict__ Wr) {
    int i = blockIdx.x * blockDim.x + threadIdx.x;
    if (i < 96 * 16) {
        int c = i >> 4, k = i & 15;
        float v = (c < 64) ? We[k * 64 + c] : Wg1[k * 32 + (c - 64)];
        g_Wt[i] = __float2half_rn(v);
    }
    if (i < 128 * 64) {
        int c = i >> 6, k = i & 63;
        float v = (c < 64) ? Wl[k * 64 + c] : Wr[k * 64 + (c - 64)];
        g_W2t[i] = __float2half_rn(v);
    }
}

// ---------------------------------------------------------------------------
// Kernel 1 (TENSOR-CORE node transforms): per warp C[32,128] =
// fp16(x[32,64]) @ [Wl|Wr] + bias via 128x mma.sync.m16n8k16 (fp32 acc).
// Fragment layouts identical to the validated k_edge mma. Also zeroes d_out
// and inits denom/gate accumulators.
// ---------------------------------------------------------------------------
#define PTPB 128
#define XS_ST 68                       // Xs stride (halfs)
#define OUT_ST 136                     // Out stride (halfs)
#define WBUF (32 * OUT_ST)             // per-warp union buffer (halfs)
#define PREP_SMEM (128 * 72 * 2 + 512 + 4 * WBUF * 2)   // 53760 bytes

__global__ void __launch_bounds__(PTPB) k_prep(
        const float* __restrict__ x,
        const float* __restrict__ bl, const float* __restrict__ br,
        float* __restrict__ out) {
    extern __shared__ __align__(16) char sdyn[];
    __half* sW    = (__half*)sdyn;                     // [128][72]
    float*  sBias = (float*)(sdyn + 128 * 72 * 2);     // [128]
    __half* bufs  = (__half*)(sBias + 128);            // 4 x WBUF

    int t = threadIdx.x, lane = t & 31, w = t >> 5;
    __half* buf = bufs + w * WBUF;
    int nb = blockIdx.x * 128;
    int nw = nb + w * 32;

    // stage weights padded (8 uint4 per column), bias, init accumulators
    {
        const uint4* wsrc = (const uint4*)g_W2t;       // 1024 x 16B
        for (int i = t; i < 1024; i += PTPB) {
            int c = i >> 3, u = i & 7;
            *(uint4*)&sW[c * 72 + u * 8] = wsrc[i];
        }
    }
    sBias[t] = (t < 64) ? bl[t] : br[t - 64];
    {
        int n = nb + t;
        if (n < NN) {
            g_denom[n] = make_float4(0.f, 0.f, 0.f, 0.f);
            g_gate2[n] = make_float2(0.f, 0.f);
        }
        float4* ob = (float4*)out + (size_t)nb * 16;
        int flim = (NN - nb) * 16;                      // valid float4s
#pragma unroll
        for (int i = 0; i < 16; i++) {
            int j = t + i * PTPB;
            if (j < flim) ob[j] = make_float4(0.f, 0.f, 0.f, 0.f);
        }
    }
    __syncthreads();

    // stage this warp's 32 x-rows as fp16 into buf (Xs layout, stride 68)
    int nlim = NN - nw;                                 // valid rows (may be <=0)
    {
        const float4* xb = (const float4*)x + (size_t)nw * 16;
#pragma unroll
        for (int i = 0; i < 16; i++) {
            int j = lane + 32 * i;                      // 0..511
            int r = j >> 4, c4 = j & 15;
            float4 v = (r < nlim) ? xb[j] : make_float4(0.f, 0.f, 0.f, 0.f);
            uint2 p;
            p.x = h2_bits(__floats2half2_rn(v.x, v.y));
            p.y = h2_bits(__floats2half2_rn(v.z, v.w));
            *(uint2*)&buf[r * XS_ST + c4 * 4] = p;
        }
    }
    __syncwarp();

    int gr = lane >> 2, q = lane & 3;

    // load ALL A fragments (2 m-tiles x 4 k-steps), then buf is reusable
    u32 A[2][4][4];
#pragma unroll
    for (int mt = 0; mt < 2; mt++)
#pragma unroll
        for (int ks = 0; ks < 4; ks++) {
            int r0 = gr + 16 * mt;
            int k0 = ks * 16 + 2 * q;
            A[mt][ks][0] = *(const u32*)&buf[r0 * XS_ST + k0];
            A[mt][ks][1] = *(const u32*)&buf[(r0 + 8) * XS_ST + k0];
            A[mt][ks][2] = *(const u32*)&buf[r0 * XS_ST + k0 + 8];
            A[mt][ks][3] = *(const u32*)&buf[(r0 + 8) * XS_ST + k0 + 8];
        }
    __syncwarp();

    // mma over 16 n-tiles; write results into buf (Out layout, stride 136)
#pragma unroll
    for (int nt = 0; nt < 16; nt++) {
        float2 bv = *(const float2*)&sBias[8 * nt + 2 * q];
        float d[2][4];
#pragma unroll
        for (int mt = 0; mt < 2; mt++) {
            d[mt][0] = bv.x; d[mt][1] = bv.y;
            d[mt][2] = bv.x; d[mt][3] = bv.y;
        }
#pragma unroll
        for (int ks = 0; ks < 4; ks++) {
            u32 b0 = *(const u32*)&sW[(8 * nt + gr) * 72 + ks * 16 + 2 * q];
            u32 b1 = *(const u32*)&sW[(8 * nt + gr) * 72 + ks * 16 + 2 * q + 8];
#pragma unroll
            for (int mt = 0; mt < 2; mt++)
                mma16816(d[mt][0], d[mt][1], d[mt][2], d[mt][3],
                         A[mt][ks][0], A[mt][ks][1], A[mt][ks][2], A[mt][ks][3],
                         b0, b1);
        }
        int col = 8 * nt + 2 * q;
#pragma unroll
        for (int mt = 0; mt < 2; mt++) {
            int r0 = gr + 16 * mt;
            *(u32*)&buf[r0 * OUT_ST + col] =
                h2_bits(__floats2half2_rn(d[mt][0], d[mt][1]));
            *(u32*)&buf[(r0 + 8) * OUT_ST + col] =
                h2_bits(__floats2half2_rn(d[mt][2], d[mt][3]));
        }
    }
    __syncwarp();

    // coalesced store: cols 0..63 -> g_xlh, 64..127 -> g_xrh
#pragma unroll
    for (int i = 0; i < 16; i++) {
        int j = lane + 32 * i;                  // 0..511 uint4 slots
        int r = j >> 4, a = (j >> 3) & 1, u = j & 7;
        if (r < nlim) {
            uint4 v = *(const uint4*)&buf[r * OUT_ST + a * 64 + u * 8];
            __half* dst = a ? g_xrh : g_xlh;
            *(uint4*)&dst[(size_t)(nw + r) * 64 + u * 8] = v;
        }
    }
}

// ---------------------------------------------------------------------------
// Kernel 2 (fused edge pass, tensor-core matmuls) — R13 champion, verbatim.
// ---------------------------------------------------------------------------
#define ETPB 128
#define RST 72
#define EAST 20

__global__ void __launch_bounds__(ETPB) k_edge(
        const int* __restrict__ ei, const float* __restrict__ eag,
        const float* __restrict__ att, const float* __restrict__ Wg2,
        const float* __restrict__ bg1, const float* __restrict__ bg2p,
        float* __restrict__ out) {
    __shared__ __align__(16) __half sXL[4][32 * RST];
    __shared__ __align__(16) __half sXR[4][32 * RST];
    __shared__ __align__(16) __half sEA[4][32 * EAST];
    __shared__ __align__(16) __half sWt[96 * 16];
    __shared__ __align__(16) float  sAtt[64];
    __shared__ __align__(8)  float  sWg2[32];
    __shared__ __align__(8)  float  sBg1[32];

    int t = threadIdx.x, lane = t & 31, w = t >> 5;
    __half* XL = sXL[w];
    __half* XR = sXR[w];
    __half* EA = sEA[w];

    for (int i = t; i < 192; i += ETPB)
        cpa16(&sWt[i * 8], &g_Wt[i * 8]);
    if (t < 64) sAtt[t] = att[t];
    if (t >= 64 && t < 96)  sWg2[t - 64] = Wg2[t - 64];
    if (t >= 96 && t < 128) sBg1[t - 96] = bg1[t - 96];

    int e = blockIdx.x * ETPB + t;
    int src = ei[e];
    int tgt = ei[EE + e];

    int rlane = lane >> 3;
    int off8  = (lane & 7) * 8;
#pragma unroll
    for (int i = 0; i < 8; i++) {
        int r  = i * 4 + rlane;
        int s  = __shfl_sync(0xFFFFFFFFu, src, r);
        int tg = __shfl_sync(0xFFFFFFFFu, tgt, r);
        cpa16(&XL[r * RST + off8], g_xlh + (size_t)s  * 64 + off8);
        cpa16(&XR[r * RST + off8], g_xrh + (size_t)tg * 64 + off8);
    }
    asm volatile("cp.async.commit_group;" ::: "memory");

    {
        const float4* eabase = (const float4*)eag
                             + (size_t)(blockIdx.x * ETPB + 32 * w) * 4;
#pragma unroll
        for (int i = 0; i < 4; i++) {
            int j = lane + 32 * i;
            float4 v = eabase[j];
            int ed = j >> 2, qq = j & 3;
            uint2 p;
            p.x = h2_bits(__floats2half2_rn(v.x, v.y));
            p.y = h2_bits(__floats2half2_rn(v.z, v.w));
            *(uint2*)&EA[ed * EAST + qq * 4] = p;
        }
    }
    float bg2v = bg2p[0];

    asm volatile("cp.async.wait_group 0;" ::: "memory");
    __syncthreads();

    int gr = lane >> 2;
    int q  = lane & 3;

    u32 a0m0 = *(const u32*)&EA[gr * EAST + 2 * q];
    u32 a1m0 = *(const u32*)&EA[(gr + 8) * EAST + 2 * q];
    u32 a2m0 = *(const u32*)&EA[gr * EAST + 2 * q + 8];
    u32 a3m0 = *(const u32*)&EA[(gr + 8) * EAST + 2 * q + 8];
    u32 a0m1 = *(const u32*)&EA[(gr + 16) * EAST + 2 * q];
    u32 a1m1 = *(const u32*)&EA[(gr + 24) * EAST + 2 * q];
    u32 a2m1 = *(const u32*)&EA[(gr + 16) * EAST + 2 * q + 8];
    u32 a3m1 = *(const u32*)&EA[(gr + 24) * EAST + 2 * q + 8];

    float ap[4][4] = {};
    float gp[4]    = {0.f, 0.f, 0.f, 0.f};

#pragma unroll
    for (int nt = 0; nt < 12; nt++) {
        u32 b0 = *(const u32*)&sWt[(8 * nt + gr) * 16 + 2 * q];
        u32 b1 = *(const u32*)&sWt[(8 * nt + gr) * 16 + 2 * q + 8];

#pragma unroll
        for (int mt = 0; mt < 2; mt++) {
            float d0 = 0.f, d1 = 0.f, d2 = 0.f, d3 = 0.f;
            if (mt == 0) mma16816(d0, d1, d2, d3, a0m0, a1m0, a2m0, a3m0, b0, b1);
            else         mma16816(d0, d1, d2, d3, a0m1, a1m1, a2m1, a3m1, b0, b1);

            int r0 = gr + 16 * mt;
            if (nt < 8) {
                int col = 8 * nt + 2 * q;
                int h   = nt >> 1;
                float2 attv = *(const float2*)&sAtt[col];
                __half2 xl2 = *(const __half2*)&XL[r0 * RST + col];
                __half2 xr2 = *(const __half2*)&XR[r0 * RST + col];
                float2 f = __half22float2(__hadd2(xl2, xr2));
                float m0 = d0 + f.x, m1 = d1 + f.y;
                ap[2 * mt][h] += leaky(m0) * attv.x + leaky(m1) * attv.y;
                xl2 = *(const __half2*)&XL[(r0 + 8) * RST + col];
                xr2 = *(const __half2*)&XR[(r0 + 8) * RST + col];
                f = __half22float2(__hadd2(xl2, xr2));
                m0 = d2 + f.x; m1 = d3 + f.y;
                ap[2 * mt + 1][h] += leaky(m0) * attv.x + leaky(m1) * attv.y;
            } else {
                int hc = 8 * (nt - 8) + 2 * q;
                float2 b1v = *(const float2*)&sBg1[hc];
                float2 w2v = *(const float2*)&sWg2[hc];
                float h0 = d0 + b1v.x, h1 = d1 + b1v.y;
                gp[2 * mt]     += h0 * sigmoidf_(h0) * w2v.x +
                                  h1 * sigmoidf_(h1) * w2v.y;
                h0 = d2 + b1v.x; h1 = d3 + b1v.y;
                gp[2 * mt + 1] += h0 * sigmoidf_(h0) * w2v.x +
                                  h1 * sigmoidf_(h1) * w2v.y;
            }
        }
    }

#pragma unroll
    for (int s = 0; s < 4; s++) {
#pragma unroll
        for (int h = 0; h < 4; h++) {
            ap[s][h] += __shfl_xor_sync(0xFFFFFFFFu, ap[s][h], 1);
            ap[s][h] += __shfl_xor_sync(0xFFFFFFFFu, ap[s][h], 2);
        }
        gp[s] += __shfl_xor_sync(0xFFFFFFFFu, gp[s], 1);
        gp[s] += __shfl_xor_sync(0xFFFFFFFFu, gp[s], 2);
    }

    int r = gr + 8 * q;
    float e0 = __expf(ap[q][0]);
    float e1 = __expf(ap[q][1]);
    float e2 = __expf(ap[q][2]);
    float e3 = __expf(ap[q][3]);
    float gate = sigmoidf_(gp[q] + bg2v);
    int tgt_r = __shfl_sync(0xFFFFFFFFu, tgt, r);

    __syncwarp();
    float* mw = (float*)XR;
    mw[r * 8 + 0] = e0; mw[r * 8 + 1] = e1;
    mw[r * 8 + 2] = e2; mw[r * 8 + 3] = e3;
    mw[r * 8 + 4] = __int_as_float(tgt_r);
    red4((float*)&g_denom[tgt_r], e0, e1, e2, e3);
    red2((float*)&g_gate2[tgt_r], gate, 1.f);
    __syncwarp();

    int q15  = lane & 15;
    int rsel = lane >> 4;
    int h_c  = q15 >> 2;
#pragma unroll
    for (int i = 0; i < 16; i++) {
        int rr   = 2 * i + rsel;
        float a  = mw[rr * 8 + h_c];
        int tg   = __float_as_int(mw[rr * 8 + 4]);
        uint2 hv = *(const uint2*)&XL[rr * RST + q15 * 4];
        float2 f01 = __half22float2(*(const __half2*)&hv.x);
        float2 f23 = __half22float2(*(const __half2*)&hv.y);
        red4(out + (size_t)tg * 64 + q15 * 4,
             f01.x * a, f01.y * a, f23.x * a, f23.y * a);
    }
}

// ---------------------------------------------------------------------------
// Kernel 3: node epilogue — R13 champion, verbatim.
// ---------------------------------------------------------------------------
__global__ void k_final(const float* __restrict__ x,
                        const float* __restrict__ conv_bias,
                        const float* __restrict__ gamma,
                        const float* __restrict__ beta,
                        float* __restrict__ out) {
    int gid = blockIdx.x * blockDim.x + threadIdx.x;
    int n = gid >> 4;
    int q = threadIdx.x & 15;
    int h = q >> 2;

    float2 gd = g_gate2[n];
    float mg = gd.x / fmaxf(gd.y, 1.f);
    float4 den4 = g_denom[n];
    float den = (h == 0) ? den4.x : (h == 1) ? den4.y : (h == 2) ? den4.z : den4.w;
    float inv = den > 0.f ? 1.f / den : 0.f;

    size_t idx = (size_t)n * 16 + q;
    float4 o  = ((const float4*)out)[idx];
    float4 cb = __ldg(&((const float4*)conv_bias)[q]);
    float4 v;
    v.x = (o.x * inv + cb.x) * mg;
    v.y = (o.y * inv + cb.y) * mg;
    v.z = (o.z * inv + cb.z) * mg;
    v.w = (o.w * inv + cb.w) * mg;

    float s  = v.x + v.y + v.z + v.w;
    float sq = v.x * v.x + v.y * v.y + v.z * v.z + v.w * v.w;
#pragma unroll
    for (int ofs = 1; ofs < 16; ofs <<= 1) {
        s  += __shfl_xor_sync(0xFFFFFFFFu, s,  ofs);
        sq += __shfl_xor_sync(0xFFFFFFFFu, sq, ofs);
    }
    float mu   = s * (1.f / 64.f);
    float var  = sq * (1.f / 64.f) - mu * mu;
    float rstd = rsqrtf(var + 1e-5f);

    float4 g  = __ldg(&((const float4*)gamma)[q]);
    float4 bt = __ldg(&((const float4*)beta)[q]);
    float4 xv = ((const float4*)x)[idx];
    float4 rr;
    float n0 = (v.x - mu) * rstd * g.x + bt.x;  n0 *= sigmoidf_(n0);  rr.x = n0 + xv.x;
    float n1 = (v.y - mu) * rstd * g.y + bt.y;  n1 *= sigmoidf_(n1);  rr.y = n1 + xv.y;
    float n2 = (v.z - mu) * rstd * g.z + bt.z;  n2 *= sigmoidf_(n2);  rr.z = n2 + xv.z;
    float n3 = (v.w - mu) * rstd * g.w + bt.w;  n3 *= sigmoidf_(n3);  rr.w = n3 + xv.w;
    ((float4*)out)[idx] = rr;
}

// ---------------------------------------------------------------------------
extern "C" void kernel_launch(void* const* d_in, const int* in_sizes, int n_in,
                              void* d_out, int out_size) {
    const float* x         = (const float*)d_in[0];
    const int*   ei        = (const int*)  d_in[1];
    const float* edge_attr = (const float*)d_in[2];
    const float* Wl        = (const float*)d_in[3];
    const float* bl        = (const float*)d_in[4];
    const float* Wr        = (const float*)d_in[5];
    const float* br        = (const float*)d_in[6];
    const float* We        = (const float*)d_in[7];
    const float* att       = (const float*)d_in[8];
    const float* conv_bias = (const float*)d_in[9];
    const float* Wg1       = (const float*)d_in[10];
    const float* bg1       = (const float*)d_in[11];
    const float* Wg2       = (const float*)d_in[12];
    const float* bg2       = (const float*)d_in[13];
    const float* gamma     = (const float*)d_in[14];
    const float* beta      = (const float*)d_in[15];
    float* out = (float*)d_out;

    cudaFuncSetAttribute(k_prep, cudaFuncAttributeMaxDynamicSharedMemorySize,
                         PREP_SMEM);

    k_wcvt <<<32, 256>>>(We, Wg1, Wl, Wr);
    k_prep <<<(NN + 127) / 128, PTPB, PREP_SMEM>>>(x, bl, br, out);
    k_edge <<<EE / ETPB, ETPB>>>(ei, edge_attr, att, Wg2, bg1, bg2, out);
    k_final<<<NN * 16 / TPB, TPB>>>(x, conv_bias, gamma, beta, out);
}